// round 12
// baseline (speedup 1.0000x reference)
#include <cuda_runtime.h>
#include <cuda_fp16.h>
#include <cstdint>

// Problem constants
#define BN 8
#define CCH 128
#define HH 128
#define WW 256
#define NI 65

// Tiling: 128-wide w tiles, 192-wide x2 window, KC=32 chunks
#define WT 128
#define KC 32
#define LDA 136     // X1s halves per k-row (128 m + 8 pad); 272B = 17*16 -> 4-bank rotation
#define LDB 200     // X2s halves per k-row (192 + 8 pad);   400B = 25*16 -> 4-bank rotation
#define LDJ 132     // cs2 floats per j-row (128 + 4 pad); 528B float4-aligned
#define JROWS 80    // j idx = (col-row)+15 wrapped mod 80; valid j -> [15,79]

#define X1BUF (KC * LDA)                 // halves
#define X2BUF (KC * LDB)
#define X1_BYTES (2 * X1BUF * 2)         // 17408
#define X2_BYTES (2 * X2BUF * 2)         // 25600
#define CS_OFF (X1_BYTES + X2_BYTES)     // 43008 (16B aligned)
#define SMEM_TOTAL (CS_OFF + JROWS * LDJ * 4)   // 85248 B -> 170.5 KB/SM @ 2 CTAs

#define GRIDX 304                        // 152 SMs x 2 resident CTAs (persistent)
#define NTILES (BN * HH * (WW / WT))     // 2048
#define CSTRIDE ((size_t)HH * WW)

__global__ __launch_bounds__(512, 2)
void corr_volume_kernel(const float* __restrict__ x1,
                        const float* __restrict__ x2,
                        float* __restrict__ out)
{
    extern __shared__ __align__(16) char smraw[];
    __half (*X1s)[X1BUF] = (__half(*)[X1BUF])smraw;
    __half (*X2s)[X2BUF] = (__half(*)[X2BUF])(smraw + X1_BYTES);
    float* cs2 = (float*)(smraw + CS_OFF);

    const int tid  = threadIdx.x;
    const int lane = tid & 31;
    const int wid  = tid >> 5;           // 0..15
    // 8x2 banded warp grid: warp (wm, wn) -> rows [m0,m0+16), band cols [nst,nst+40)
    const int wm   = wid >> 1;           // 0..7
    const int wn   = wid & 1;
    const int m0   = wm * 16;
    const int nst  = m0 + wn * 40;

    const uint32_t x1s_base = (uint32_t)__cvta_generic_to_shared(X1s);
    const uint32_t x2s_base = (uint32_t)__cvta_generic_to_shared(X2s);
    const int r = lane & 7;
    const uint32_t addrA0 = x1s_base +
        2u * ((uint32_t)((r + ((lane >> 4) & 1) * 8) * LDA + (m0 + ((lane >> 3) & 1) * 8)));
    const uint32_t addrB0 = x2s_base +
        2u * ((uint32_t)((r + ((lane >> 3) & 1) * 8) * LDB + (nst + ((lane >> 4) & 1) * 8)));

    // ---- A load roles: thread -> (k-row cr1a + 16*it, m-col co1), 2 float4 ----
    const int cr1a = tid >> 5;           // 0..15
    const int co1  = (tid & 31) * 4;     // 0..124

    // ---- B load roles: 3 tasks/thread over 32 k-rows x 48 float4-cols ----
    size_t  boff[3];     // gmem offset (floats) from pB
    uint32_t bsoff[3];   // smem byte offset within X2s buffer
    bool    bsafe[3];    // col*4 >= 64 (no left-pad needed even at bx==0)
    #pragma unroll
    for (int it = 0; it < 3; it++) {
        int idx = tid + it * 512;
        int br  = idx / 48;
        int bc4 = idx % 48;
        boff[it]  = (size_t)br * CSTRIDE + (size_t)bc4 * 4;
        bsoff[it] = (uint32_t)(br * (LDB * 2) + bc4 * 8);
        bsafe[it] = (bc4 >= 16);
    }

    float acc[5][4];
    float4 p1[2], p2[3];

    // per-tile base pointers (pA includes thread offsets; pB is w-base only)
    auto tile_pA = [&](int t) -> const float* {
        int bx = t & 1, h = (t >> 1) & (HH - 1), n = t >> 8;
        return x1 + ((size_t)n * CCH * HH + (size_t)h) * WW + bx * WT
                  + (size_t)cr1a * CSTRIDE + co1;
    };
    auto tile_pB = [&](int t) -> const float* {
        int bx = t & 1, h = (t >> 1) & (HH - 1), n = t >> 8;
        return x2 + ((size_t)n * CCH * HH + (size_t)h) * WW + (bx * WT - 64);
    };

    auto load_chunk = [&](const float* pA, const float* pB, bool bx0, int kc) {
        #pragma unroll
        for (int it = 0; it < 2; it++)
            p1[it] = *(const float4*)(pA + (size_t)(kc * KC + it * 16) * CSTRIDE);
        #pragma unroll
        for (int it = 0; it < 3; it++) {
            if (!bx0 || bsafe[it])
                p2[it] = *(const float4*)(pB + (size_t)(kc * KC) * CSTRIDE + boff[it]);
            else
                p2[it] = make_float4(0.f, 0.f, 0.f, 0.f);
        }
    };
    auto store_chunk = [&](int buf) {
        #pragma unroll
        for (int it = 0; it < 2; it++) {
            __half2* d = (__half2*)&X1s[buf][(cr1a + it * 16) * LDA + co1];
            d[0] = __floats2half2_rn(p1[it].x, p1[it].y);
            d[1] = __floats2half2_rn(p1[it].z, p1[it].w);
        }
        #pragma unroll
        for (int it = 0; it < 3; it++) {
            __half2* d = (__half2*)((char*)X2s[buf] + bsoff[it]);
            d[0] = __floats2half2_rn(p2[it].x, p2[it].y);
            d[1] = __floats2half2_rn(p2[it].z, p2[it].w);
        }
    };

    auto mma_phase = [&](int buf) {
        const uint32_t offA = (uint32_t)(buf * X1BUF * 2);
        const uint32_t offB = (uint32_t)(buf * X2BUF * 2);
        #pragma unroll
        for (int ks = 0; ks < KC / 16; ks++) {
            uint32_t a[4];
            {
                uint32_t aaddr = addrA0 + offA + 2u * (uint32_t)(ks * 16 * LDA);
                asm volatile(
                    "ldmatrix.sync.aligned.m8n8.x4.trans.shared.b16 {%0,%1,%2,%3}, [%4];\n"
                    : "=r"(a[0]), "=r"(a[1]), "=r"(a[2]), "=r"(a[3]) : "r"(aaddr));
            }
            #pragma unroll
            for (int p = 0; p < 2; p++) {
                uint32_t b0, b1, b2, b3;
                uint32_t baddr = addrB0 + offB + 2u * (uint32_t)(ks * 16 * LDB + p * 16);
                asm volatile(
                    "ldmatrix.sync.aligned.m8n8.x4.trans.shared.b16 {%0,%1,%2,%3}, [%4];\n"
                    : "=r"(b0), "=r"(b1), "=r"(b2), "=r"(b3) : "r"(baddr));
                asm volatile(
                    "mma.sync.aligned.m16n8k16.row.col.f32.f16.f16.f32 "
                    "{%0,%1,%2,%3}, {%4,%5,%6,%7}, {%8,%9}, {%0,%1,%2,%3};\n"
                    : "+f"(acc[2*p][0]), "+f"(acc[2*p][1]), "+f"(acc[2*p][2]), "+f"(acc[2*p][3])
                    : "r"(a[0]), "r"(a[1]), "r"(a[2]), "r"(a[3]), "r"(b0), "r"(b1));
                asm volatile(
                    "mma.sync.aligned.m16n8k16.row.col.f32.f16.f16.f32 "
                    "{%0,%1,%2,%3}, {%4,%5,%6,%7}, {%8,%9}, {%0,%1,%2,%3};\n"
                    : "+f"(acc[2*p+1][0]), "+f"(acc[2*p+1][1]), "+f"(acc[2*p+1][2]), "+f"(acc[2*p+1][3])
                    : "r"(a[0]), "r"(a[1]), "r"(a[2]), "r"(a[3]), "r"(b2), "r"(b3));
            }
            {
                uint32_t b0, b1;
                uint32_t baddr = addrB0 + offB + 2u * (uint32_t)(ks * 16 * LDB + 32);
                asm volatile(
                    "ldmatrix.sync.aligned.m8n8.x2.trans.shared.b16 {%0,%1}, [%2];\n"
                    : "=r"(b0), "=r"(b1) : "r"(baddr));
                asm volatile(
                    "mma.sync.aligned.m16n8k16.row.col.f32.f16.f16.f32 "
                    "{%0,%1,%2,%3}, {%4,%5,%6,%7}, {%8,%9}, {%0,%1,%2,%3};\n"
                    : "+f"(acc[4][0]), "+f"(acc[4][1]), "+f"(acc[4][2]), "+f"(acc[4][3])
                    : "r"(a[0]), "r"(a[1]), "r"(a[2]), "r"(a[3]), "r"(b0), "r"(b1));
            }
        }
    };

    int t = blockIdx.x;
    if (t >= NTILES) return;

    const float* pA = tile_pA(t);
    const float* pB = tile_pB(t);
    bool bx0 = ((t & 1) == 0);

    // prologue: c0 -> b0; sync; then load c1 (no barrier crossed before its store)
    load_chunk(pA, pB, bx0, 0);
    store_chunk(0);
    __syncthreads();
    load_chunk(pA, pB, bx0, 1);

    while (true) {
        const int tn = t + GRIDX;
        const bool has_next = (tn < NTILES);

        #pragma unroll
        for (int i5 = 0; i5 < 5; i5++)
            #pragma unroll
            for (int j = 0; j < 4; j++) acc[i5][j] = 0.f;

        // kc0: MMA b0 (c0); store c1 -> b1.
        mma_phase(0);
        store_chunk(1);
        __syncthreads();

        // kc1: load c2; MMA b1 (c1); store c2 -> b0.
        load_chunk(pA, pB, bx0, 2);
        mma_phase(1);
        store_chunk(0);
        __syncthreads();

        // kc2: load c3; MMA b0 (c2); store c3 -> b1.
        load_chunk(pA, pB, bx0, 3);
        mma_phase(0);
        store_chunk(1);
        __syncthreads();

        // kc3: load next-c0; MMA b1 (c3); store next-c0 -> b0.
        const float* pAN = has_next ? tile_pA(tn) : pA;
        const float* pBN = has_next ? tile_pB(tn) : pB;
        const bool bx0N = has_next ? ((tn & 1) == 0) : false;
        if (has_next)
            load_chunk(pAN, pBN, bx0N, 0);
        mma_phase(1);
        if (has_next)
            store_chunk(0);

        // band staging (per-warp private; precedes the single barrier)
        {
            const int rowa = m0 + (lane >> 2);
            #pragma unroll
            for (int t8 = 0; t8 < 5; t8++) {
                int colb = nst + t8 * 8 + 2 * (lane & 3);
                int j0 = colb - rowa + 15;
                int ja = j0;     if (ja >= JROWS) ja -= JROWS;
                int jb = j0 + 1; if (jb >= JROWS) jb -= JROWS;
                int jc = j0 - 8; if (jc >= JROWS) jc -= JROWS;
                int jd = j0 - 7; if (jd >= JROWS) jd -= JROWS;
                cs2[ja * LDJ + rowa]     = acc[t8][0];
                cs2[jb * LDJ + rowa]     = acc[t8][1];
                cs2[jc * LDJ + rowa + 8] = acc[t8][2];
                cs2[jd * LDJ + rowa + 8] = acc[t8][3];
            }
        }

        __syncthreads();   // staging visible; fences b0 store

        // prefetch next tile's c1 after the barrier (in flight through output+kc0)
        if (has_next)
            load_chunk(pAN, pBN, bx0N, 1);

        // vectorized de-band output: 128 cols per i-row, 32 float4
        {
            const int bx = t & 1, h = (t >> 1) & (HH - 1), n = t >> 8;
            const int q    = tid & 31;
            const int rowi = tid >> 5;            // 0..15
            float* ob = out + (((size_t)n * NI) * HH + h) * WW + bx * WT + 4 * q;
            #pragma unroll
            for (int it = 0; it < 5; it++) {
                int i = it * 16 + rowi;
                if (i < NI) {
                    float4 v = *(const float4*)(cs2 + (79 - i) * LDJ + 4 * q);
                    v.x *= (1.0f / 128.0f); v.y *= (1.0f / 128.0f);
                    v.z *= (1.0f / 128.0f); v.w *= (1.0f / 128.0f);
                    *(float4*)(ob + (size_t)i * HH * WW) = v;
                }
            }
        }
        // cs2 reads complete before next staging (4 barriers away)

        if (!has_next) break;
        t = tn;
        pA = pAN; pB = pBN; bx0 = bx0N;
    }
}

extern "C" void kernel_launch(void* const* d_in, const int* in_sizes, int n_in,
                              void* d_out, int out_size)
{
    const float* x1 = (const float*)d_in[0];
    const float* x2 = (const float*)d_in[1];
    float* out = (float*)d_out;
    (void)in_sizes; (void)n_in; (void)out_size;

    cudaFuncSetAttribute(corr_volume_kernel,
                         cudaFuncAttributeMaxDynamicSharedMemorySize, SMEM_TOTAL);

    dim3 grid(GRIDX);
    dim3 block(512);
    corr_volume_kernel<<<grid, block, SMEM_TOTAL>>>(x1, x2, out);
}

// round 13
// speedup vs baseline: 1.0014x; 1.0014x over previous
#include <cuda_runtime.h>
#include <cuda_fp16.h>
#include <cstdint>

// Problem constants
#define BN 8
#define CCH 128
#define HH 128
#define WW 256
#define NI 65

// Tiling
#define WT 64
#define KC 32
#define LDA 72      // X1s stride in halves
#define LDB 136     // X2s stride in halves
#define LDJ 68      // cs2 stride in floats (272B = 17*16)
#define JROWS 80    // idx=(j+15) wrapped mod 80; valid j -> [15,79]

#define X1BUF (KC * LDA)
#define X2BUF (KC * LDB)

#define GRIDX 592                      // 148 SMs x 4 resident CTAs (persistent)
#define NTILES (BN * HH * (WW / WT))   // 4096
#define CSTRIDE ((size_t)HH * WW)

__global__ __launch_bounds__(256, 4)
void corr_volume_kernel(const float* __restrict__ x1,
                        const float* __restrict__ x2,
                        float* __restrict__ out)
{
    __shared__ __align__(16) __half X1s[2][X1BUF];     //  9216 B
    __shared__ __align__(16) __half X2s[2][X2BUF];     // 17408 B
    __shared__ __align__(16) float  cs2[JROWS * LDJ];  // 21760 B (48384 total, STATIC)

    const int tid  = threadIdx.x;
    const int lane = tid & 31;
    const int wid  = tid >> 5;
    const int wm   = wid >> 1;
    const int wn   = wid & 1;
    const int m0   = wm * 16;
    const int nst  = m0 + wn * 40;

    const uint32_t x1s_base = (uint32_t)__cvta_generic_to_shared(X1s);
    const uint32_t x2s_base = (uint32_t)__cvta_generic_to_shared(X2s);
    const int r = lane & 7;
    const uint32_t addrA0 = x1s_base +
        2u * ((uint32_t)((r + ((lane >> 4) & 1) * 8) * LDA + (m0 + ((lane >> 3) & 1) * 8)));
    const uint32_t addrB0 = x2s_base +
        2u * ((uint32_t)((r + ((lane >> 3) & 1) * 8) * LDB + (nst + ((lane >> 4) & 1) * 8)));

    // fixed per-thread load coordinates
    const int cr1a = tid >> 4;
    const int co1  = (tid & 15) * 4;
    const int cr2a = tid >> 5;
    const int co2  = (tid & 31) * 4;

    float acc[5][4];
    float4 p1[2], p2[4];

    auto tile_pA = [&](int t) -> const float* {
        int bx = t & 3, h = (t >> 2) & (HH - 1), n = t >> 9;
        return x1 + ((size_t)n * CCH * HH + (size_t)h) * WW + bx * WT
                  + (size_t)cr1a * CSTRIDE + co1;
    };
    auto tile_pB = [&](int t) -> const float* {
        int bx = t & 3, h = (t >> 2) & (HH - 1), n = t >> 9;
        return x2 + ((size_t)n * CCH * HH + (size_t)h) * WW + (bx * WT - 64)
                  + (size_t)cr2a * CSTRIDE + co2;
    };

    auto load_chunk = [&](const float* pA, const float* pB, bool ok, int kc) {
        #pragma unroll
        for (int it = 0; it < 2; it++)
            p1[it] = *(const float4*)(pA + (size_t)(kc * KC + it * 16) * CSTRIDE);
        #pragma unroll
        for (int it = 0; it < 4; it++) {
            if (ok)
                p2[it] = *(const float4*)(pB + (size_t)(kc * KC + it * 8) * CSTRIDE);
            else
                p2[it] = make_float4(0.f, 0.f, 0.f, 0.f);
        }
    };
    auto store_chunk = [&](int buf) {
        #pragma unroll
        for (int it = 0; it < 2; it++) {
            __half2* d = (__half2*)&X1s[buf][(cr1a + it * 16) * LDA + co1];
            d[0] = __floats2half2_rn(p1[it].x, p1[it].y);
            d[1] = __floats2half2_rn(p1[it].z, p1[it].w);
        }
        #pragma unroll
        for (int it = 0; it < 4; it++) {
            __half2* d = (__half2*)&X2s[buf][(cr2a + it * 8) * LDB + co2];
            d[0] = __floats2half2_rn(p2[it].x, p2[it].y);
            d[1] = __floats2half2_rn(p2[it].z, p2[it].w);
        }
    };

    auto mma_phase = [&](int buf) {
        const uint32_t offA = (uint32_t)(buf * X1BUF * 2);
        const uint32_t offB = (uint32_t)(buf * X2BUF * 2);
        #pragma unroll
        for (int ks = 0; ks < KC / 16; ks++) {
            uint32_t a[4];
            {
                uint32_t aaddr = addrA0 + offA + 2u * (uint32_t)(ks * 16 * LDA);
                asm volatile(
                    "ldmatrix.sync.aligned.m8n8.x4.trans.shared.b16 {%0,%1,%2,%3}, [%4];\n"
                    : "=r"(a[0]), "=r"(a[1]), "=r"(a[2]), "=r"(a[3]) : "r"(aaddr));
            }
            #pragma unroll
            for (int p = 0; p < 2; p++) {
                uint32_t b0, b1, b2, b3;
                uint32_t baddr = addrB0 + offB + 2u * (uint32_t)(ks * 16 * LDB + p * 16);
                asm volatile(
                    "ldmatrix.sync.aligned.m8n8.x4.trans.shared.b16 {%0,%1,%2,%3}, [%4];\n"
                    : "=r"(b0), "=r"(b1), "=r"(b2), "=r"(b3) : "r"(baddr));
                asm volatile(
                    "mma.sync.aligned.m16n8k16.row.col.f32.f16.f16.f32 "
                    "{%0,%1,%2,%3}, {%4,%5,%6,%7}, {%8,%9}, {%0,%1,%2,%3};\n"
                    : "+f"(acc[2*p][0]), "+f"(acc[2*p][1]), "+f"(acc[2*p][2]), "+f"(acc[2*p][3])
                    : "r"(a[0]), "r"(a[1]), "r"(a[2]), "r"(a[3]), "r"(b0), "r"(b1));
                asm volatile(
                    "mma.sync.aligned.m16n8k16.row.col.f32.f16.f16.f32 "
                    "{%0,%1,%2,%3}, {%4,%5,%6,%7}, {%8,%9}, {%0,%1,%2,%3};\n"
                    : "+f"(acc[2*p+1][0]), "+f"(acc[2*p+1][1]), "+f"(acc[2*p+1][2]), "+f"(acc[2*p+1][3])
                    : "r"(a[0]), "r"(a[1]), "r"(a[2]), "r"(a[3]), "r"(b2), "r"(b3));
            }
            {
                uint32_t b0, b1;
                uint32_t baddr = addrB0 + offB + 2u * (uint32_t)(ks * 16 * LDB + 32);
                asm volatile(
                    "ldmatrix.sync.aligned.m8n8.x2.trans.shared.b16 {%0,%1}, [%2];\n"
                    : "=r"(b0), "=r"(b1) : "r"(baddr));
                asm volatile(
                    "mma.sync.aligned.m16n8k16.row.col.f32.f16.f16.f32 "
                    "{%0,%1,%2,%3}, {%4,%5,%6,%7}, {%8,%9}, {%0,%1,%2,%3};\n"
                    : "+f"(acc[4][0]), "+f"(acc[4][1]), "+f"(acc[4][2]), "+f"(acc[4][3])
                    : "r"(a[0]), "r"(a[1]), "r"(a[2]), "r"(a[3]), "r"(b0), "r"(b1));
            }
        }
    };

    int t = blockIdx.x;
    if (t >= NTILES) return;

    const float* pA = tile_pA(t);
    const float* pB = tile_pB(t);
    bool ok = ((t & 3) != 0) || (co2 >= 64);

    // prologue: c0 -> b0; sync; load c1 (STS'd at phase0 top, crosses no barrier)
    load_chunk(pA, pB, ok, 0);
    store_chunk(0);
    __syncthreads();
    load_chunk(pA, pB, ok, 1);

    while (true) {
        const int tn = t + GRIDX;
        const bool has_next = (tn < NTILES);
        const float* pAN = has_next ? tile_pA(tn) : pA;
        const float* pBN = has_next ? tile_pB(tn) : pB;
        const bool okN = has_next ? (((tn & 3) != 0) || (co2 >= 64)) : false;

        #pragma unroll
        for (int i5 = 0; i5 < 5; i5++)
            #pragma unroll
            for (int j = 0; j < 4; j++) acc[i5][j] = 0.f;

        // Deferred-store pipeline (distance 2): phase k stores chunk k+1 (data
        // long-arrived), issues LDG for chunk k+2, MMAs buf k&1, syncs. Barriers
        // drain only ready STS; each LDG gets a full phase + barrier to land.

        // phase0: STS c1 -> b1; LDG c2; MMA b0 (c0)
        store_chunk(1);
        load_chunk(pA, pB, ok, 2);
        mma_phase(0);
        __syncthreads();

        // phase1: STS c2 -> b0; LDG c3; MMA b1 (c1)
        store_chunk(0);
        load_chunk(pA, pB, ok, 3);
        mma_phase(1);
        __syncthreads();

        // phase2: STS c3 -> b1; LDG next-c0; MMA b0 (c2)
        store_chunk(1);
        if (has_next)
            load_chunk(pAN, pBN, okN, 0);
        mma_phase(0);
        __syncthreads();

        // phase3: STS next-c0 -> b0; MMA b1 (c3)
        if (has_next)
            store_chunk(0);
        mma_phase(1);

        // band staging (per-warp private; precedes the single epilogue barrier)
        {
            const int rowa = m0 + (lane >> 2);
            #pragma unroll
            for (int t8 = 0; t8 < 5; t8++) {
                int colb = nst + t8 * 8 + 2 * (lane & 3);
                int j0 = colb - rowa + 15;
                int ja = j0;     if (ja >= JROWS) ja -= JROWS;
                int jb = j0 + 1; if (jb >= JROWS) jb -= JROWS;
                int jc = j0 - 8; if (jc >= JROWS) jc -= JROWS;
                int jd = j0 - 7; if (jd >= JROWS) jd -= JROWS;
                cs2[ja * LDJ + rowa]     = acc[t8][0];
                cs2[jb * LDJ + rowa]     = acc[t8][1];
                cs2[jc * LDJ + rowa + 8] = acc[t8][2];
                cs2[jd * LDJ + rowa + 8] = acc[t8][3];
            }
        }

        __syncthreads();   // staging visible; fences b0 store

        // LDG next-c1 after the barrier: in flight during output STGs and next
        // phase0's MMA; STS'd at next phase0 top with no barrier crossed.
        if (has_next)
            load_chunk(pAN, pBN, okN, 1);

        // vectorized de-band output
        {
            const int bx = t & 3, h = (t >> 2) & (HH - 1), n = t >> 9;
            const int q    = tid & 15;
            const int rowi = tid >> 4;
            float* ob = out + (((size_t)n * NI) * HH + h) * WW + bx * WT + 4 * q;
            #pragma unroll
            for (int it = 0; it < 5; it++) {
                int i = it * 16 + rowi;
                if (i < NI) {
                    float4 v = *(const float4*)(cs2 + (79 - i) * LDJ + 4 * q);
                    v.x *= (1.0f / 128.0f); v.y *= (1.0f / 128.0f);
                    v.z *= (1.0f / 128.0f); v.w *= (1.0f / 128.0f);
                    *(float4*)(ob + (size_t)i * HH * WW) = v;
                }
            }
        }
        // cs2 reads complete before next staging (4 barriers away)

        if (!has_next) break;
        t = tn;
        pA = pAN; pB = pBN; ok = okN;
    }
}

extern "C" void kernel_launch(void* const* d_in, const int* in_sizes, int n_in,
                              void* d_out, int out_size)
{
    const float* x1 = (const float*)d_in[0];
    const float* x2 = (const float*)d_in[1];
    float* out = (float*)d_out;
    (void)in_sizes; (void)n_in; (void)out_size;

    dim3 grid(GRIDX);
    dim3 block(256);
    corr_volume_kernel<<<grid, block>>>(x1, x2, out);
}

// round 14
// speedup vs baseline: 1.0763x; 1.0748x over previous
#include <cuda_runtime.h>
#include <cuda_fp16.h>
#include <cstdint>

// Problem constants
#define BN 8
#define CCH 128
#define HH 128
#define WW 256
#define NI 65

// Tiling
#define WT 64
#define KC 32
#define LDA 72      // X1s stride in halves
#define LDB 136     // X2s stride in halves
#define LDJ 68      // cs2 stride in floats (272B = 17*16)
#define JROWS 80    // idx=(j+15) wrapped mod 80; valid j -> [15,79]

#define X1BUF (KC * LDA)
#define X2BUF (KC * LDB)

#define GRIDX 444                      // 148 SMs x 3 resident CTAs (persistent)
#define NTILES (BN * HH * (WW / WT))   // 4096
#define CSTRIDE ((size_t)HH * WW)

__global__ __launch_bounds__(256, 3)
void corr_volume_kernel(const float* __restrict__ x1,
                        const float* __restrict__ x2,
                        float* __restrict__ out)
{
    __shared__ __align__(16) __half X1s[2][X1BUF];     //  9216 B
    __shared__ __align__(16) __half X2s[2][X2BUF];     // 17408 B
    __shared__ __align__(16) float  cs2[JROWS * LDJ];  // 21760 B (48384 static; x3 = 145K/SM)

    const int tid  = threadIdx.x;
    const int lane = tid & 31;
    const int wid  = tid >> 5;
    const int wm   = wid >> 1;
    const int wn   = wid & 1;
    const int m0   = wm * 16;
    const int nst  = m0 + wn * 40;

    const uint32_t x1s_base = (uint32_t)__cvta_generic_to_shared(X1s);
    const uint32_t x2s_base = (uint32_t)__cvta_generic_to_shared(X2s);
    const int r = lane & 7;
    const uint32_t addrA0 = x1s_base +
        2u * ((uint32_t)((r + ((lane >> 4) & 1) * 8) * LDA + (m0 + ((lane >> 3) & 1) * 8)));
    const uint32_t addrB0 = x2s_base +
        2u * ((uint32_t)((r + ((lane >> 3) & 1) * 8) * LDB + (nst + ((lane >> 4) & 1) * 8)));

    // fixed per-thread load coordinates
    const int cr1a = tid >> 4;
    const int co1  = (tid & 15) * 4;
    const int cr2a = tid >> 5;
    const int co2  = (tid & 31) * 4;

    float acc[5][4];
    float4 p1[2], p2[4];

    auto tile_pA = [&](int t) -> const float* {
        int bx = t & 3, h = (t >> 2) & (HH - 1), n = t >> 9;
        return x1 + ((size_t)n * CCH * HH + (size_t)h) * WW + bx * WT
                  + (size_t)cr1a * CSTRIDE + co1;
    };
    auto tile_pB = [&](int t) -> const float* {
        int bx = t & 3, h = (t >> 2) & (HH - 1), n = t >> 9;
        return x2 + ((size_t)n * CCH * HH + (size_t)h) * WW + (bx * WT - 64)
                  + (size_t)cr2a * CSTRIDE + co2;
    };

    auto load_chunk = [&](const float* pA, const float* pB, bool ok, int kc) {
        #pragma unroll
        for (int it = 0; it < 2; it++)
            p1[it] = *(const float4*)(pA + (size_t)(kc * KC + it * 16) * CSTRIDE);
        #pragma unroll
        for (int it = 0; it < 4; it++) {
            if (ok)
                p2[it] = *(const float4*)(pB + (size_t)(kc * KC + it * 8) * CSTRIDE);
            else
                p2[it] = make_float4(0.f, 0.f, 0.f, 0.f);
        }
    };
    auto store_chunk = [&](int buf) {
        #pragma unroll
        for (int it = 0; it < 2; it++) {
            __half2* d = (__half2*)&X1s[buf][(cr1a + it * 16) * LDA + co1];
            d[0] = __floats2half2_rn(p1[it].x, p1[it].y);
            d[1] = __floats2half2_rn(p1[it].z, p1[it].w);
        }
        #pragma unroll
        for (int it = 0; it < 4; it++) {
            __half2* d = (__half2*)&X2s[buf][(cr2a + it * 8) * LDB + co2];
            d[0] = __floats2half2_rn(p2[it].x, p2[it].y);
            d[1] = __floats2half2_rn(p2[it].z, p2[it].w);
        }
    };

    auto mma_phase = [&](int buf) {
        const uint32_t offA = (uint32_t)(buf * X1BUF * 2);
        const uint32_t offB = (uint32_t)(buf * X2BUF * 2);
        #pragma unroll
        for (int ks = 0; ks < KC / 16; ks++) {
            uint32_t a[4];
            {
                uint32_t aaddr = addrA0 + offA + 2u * (uint32_t)(ks * 16 * LDA);
                asm volatile(
                    "ldmatrix.sync.aligned.m8n8.x4.trans.shared.b16 {%0,%1,%2,%3}, [%4];\n"
                    : "=r"(a[0]), "=r"(a[1]), "=r"(a[2]), "=r"(a[3]) : "r"(aaddr));
            }
            #pragma unroll
            for (int p = 0; p < 2; p++) {
                uint32_t b0, b1, b2, b3;
                uint32_t baddr = addrB0 + offB + 2u * (uint32_t)(ks * 16 * LDB + p * 16);
                asm volatile(
                    "ldmatrix.sync.aligned.m8n8.x4.trans.shared.b16 {%0,%1,%2,%3}, [%4];\n"
                    : "=r"(b0), "=r"(b1), "=r"(b2), "=r"(b3) : "r"(baddr));
                asm volatile(
                    "mma.sync.aligned.m16n8k16.row.col.f32.f16.f16.f32 "
                    "{%0,%1,%2,%3}, {%4,%5,%6,%7}, {%8,%9}, {%0,%1,%2,%3};\n"
                    : "+f"(acc[2*p][0]), "+f"(acc[2*p][1]), "+f"(acc[2*p][2]), "+f"(acc[2*p][3])
                    : "r"(a[0]), "r"(a[1]), "r"(a[2]), "r"(a[3]), "r"(b0), "r"(b1));
                asm volatile(
                    "mma.sync.aligned.m16n8k16.row.col.f32.f16.f16.f32 "
                    "{%0,%1,%2,%3}, {%4,%5,%6,%7}, {%8,%9}, {%0,%1,%2,%3};\n"
                    : "+f"(acc[2*p+1][0]), "+f"(acc[2*p+1][1]), "+f"(acc[2*p+1][2]), "+f"(acc[2*p+1][3])
                    : "r"(a[0]), "r"(a[1]), "r"(a[2]), "r"(a[3]), "r"(b2), "r"(b3));
            }
            {
                uint32_t b0, b1;
                uint32_t baddr = addrB0 + offB + 2u * (uint32_t)(ks * 16 * LDB + 32);
                asm volatile(
                    "ldmatrix.sync.aligned.m8n8.x2.trans.shared.b16 {%0,%1}, [%2];\n"
                    : "=r"(b0), "=r"(b1) : "r"(baddr));
                asm volatile(
                    "mma.sync.aligned.m16n8k16.row.col.f32.f16.f16.f32 "
                    "{%0,%1,%2,%3}, {%4,%5,%6,%7}, {%8,%9}, {%0,%1,%2,%3};\n"
                    : "+f"(acc[4][0]), "+f"(acc[4][1]), "+f"(acc[4][2]), "+f"(acc[4][3])
                    : "r"(a[0]), "r"(a[1]), "r"(a[2]), "r"(a[3]), "r"(b0), "r"(b1));
            }
        }
    };

    int t = blockIdx.x;
    if (t >= NTILES) return;

    const float* pA = tile_pA(t);
    const float* pB = tile_pB(t);
    bool ok = ((t & 3) != 0) || (co2 >= 64);

    // prologue: c0 -> b0; sync; load c1 (STS'd at phase0 top)
    load_chunk(pA, pB, ok, 0);
    store_chunk(0);
    __syncthreads();
    load_chunk(pA, pB, ok, 1);

    while (true) {
        const int tn = t + GRIDX;
        const bool has_next = (tn < NTILES);
        const float* pAN = has_next ? tile_pA(tn) : pA;
        const float* pBN = has_next ? tile_pB(tn) : pB;
        const bool okN = has_next ? (((tn & 3) != 0) || (co2 >= 64)) : false;

        #pragma unroll
        for (int i5 = 0; i5 < 5; i5++)
            #pragma unroll
            for (int j = 0; j < 4; j++) acc[i5][j] = 0.f;

        // Deferred-store pipeline (distance 2), now with reg headroom (84):
        // phase k: STS c(k+1) (data long-arrived) -> buf((k+1)&1); LDG c(k+2);
        // MMA buf(k&1); sync. Barriers drain only ready STS.

        // phase0: STS c1 -> b1; LDG c2; MMA b0 (c0)
        store_chunk(1);
        load_chunk(pA, pB, ok, 2);
        mma_phase(0);
        __syncthreads();

        // phase1: STS c2 -> b0; LDG c3; MMA b1 (c1)
        store_chunk(0);
        load_chunk(pA, pB, ok, 3);
        mma_phase(1);
        __syncthreads();

        // phase2: STS c3 -> b1; LDG next-c0; MMA b0 (c2)
        store_chunk(1);
        if (has_next)
            load_chunk(pAN, pBN, okN, 0);
        mma_phase(0);
        __syncthreads();

        // phase3: STS next-c0 -> b0; MMA b1 (c3)
        if (has_next)
            store_chunk(0);
        mma_phase(1);

        // band staging (per-warp private; precedes the single epilogue barrier)
        {
            const int rowa = m0 + (lane >> 2);
            #pragma unroll
            for (int t8 = 0; t8 < 5; t8++) {
                int colb = nst + t8 * 8 + 2 * (lane & 3);
                int j0 = colb - rowa + 15;
                int ja = j0;     if (ja >= JROWS) ja -= JROWS;
                int jb = j0 + 1; if (jb >= JROWS) jb -= JROWS;
                int jc = j0 - 8; if (jc >= JROWS) jc -= JROWS;
                int jd = j0 - 7; if (jd >= JROWS) jd -= JROWS;
                cs2[ja * LDJ + rowa]     = acc[t8][0];
                cs2[jb * LDJ + rowa]     = acc[t8][1];
                cs2[jc * LDJ + rowa + 8] = acc[t8][2];
                cs2[jd * LDJ + rowa + 8] = acc[t8][3];
            }
        }

        __syncthreads();   // staging visible; fences b0 store

        // LDG next-c1 after the barrier: in flight during output STGs and next
        // phase0's MMA; STS'd at next phase0 top.
        if (has_next)
            load_chunk(pAN, pBN, okN, 1);

        // vectorized de-band output (streaming stores; out never re-read)
        {
            const int bx = t & 3, h = (t >> 2) & (HH - 1), n = t >> 9;
            const int q    = tid & 15;
            const int rowi = tid >> 4;
            float* ob = out + (((size_t)n * NI) * HH + h) * WW + bx * WT + 4 * q;
            #pragma unroll
            for (int it = 0; it < 5; it++) {
                int i = it * 16 + rowi;
                if (i < NI) {
                    float4 v = *(const float4*)(cs2 + (79 - i) * LDJ + 4 * q);
                    v.x *= (1.0f / 128.0f); v.y *= (1.0f / 128.0f);
                    v.z *= (1.0f / 128.0f); v.w *= (1.0f / 128.0f);
                    __stcs((float4*)(ob + (size_t)i * HH * WW), v);
                }
            }
        }
        // cs2 reads complete before next staging (4 barriers away)

        if (!has_next) break;
        t = tn;
        pA = pAN; pB = pBN; ok = okN;
    }
}

extern "C" void kernel_launch(void* const* d_in, const int* in_sizes, int n_in,
                              void* d_out, int out_size)
{
    const float* x1 = (const float*)d_in[0];
    const float* x2 = (const float*)d_in[1];
    float* out = (float*)d_out;
    (void)in_sizes; (void)n_in; (void)out_size;

    dim3 grid(GRIDX);
    dim3 block(256);
    corr_volume_kernel<<<grid, block>>>(x1, x2, out);
}